// round 14
// baseline (speedup 1.0000x reference)
#include <cuda_runtime.h>
#include <stdint.h>

// PluginEmbedding: sparse embedding lookup + per-row sum combine.
//   d_in[0] table         float32 [1000000, 128]
//   d_in[1] row_offsets   int32   [212993]
//   d_in[2] value_tensors int32   [212992]
// Output: float32 [212992, 128]
//
// R13 falsified the L2-hint theory (DRAM traffic unchanged at ~156MB) and the
// 256b loads spilled (regs=64). Series conclusion: DRAM%~60 is the chip's
// random-512B-gather + streaming-write ceiling. This round reverts to the R10
// core (batch=4 gathers off an SMEM metadata stage, 128-bit __ldg, __stcs
// streaming stores, 32-bit addressing) and fixes wave quantization:
// 256 rows/block -> 832 blocks = ONE full wave at 6 blocks/SM (R10's 1664
// blocks ran 1.87 waves with a ragged tail).

static constexpr int  kVocab        = 1000000;
static constexpr long long kNumRows = 8192LL * 26LL; // 212992
static constexpr int  kRowsPerBlock = 256;           // 832 blocks (exact)
static constexpr int  kBatch        = 4;             // gathers in flight / warp
static constexpr int  kRowBytes     = 512;           // 128 floats

__global__ __launch_bounds__(256, 6) void pe_gather_kernel(
    const float* __restrict__ table,
    const int*   __restrict__ row_offsets,
    const int*   __restrict__ vals,
    float*       __restrict__ out)
{
    __shared__ int s_idx[kRowsPerBlock];
    __shared__ int s_beg[kRowsPerBlock];
    __shared__ int s_end[kRowsPerBlock];

    const int t = threadIdx.x;
    const unsigned blockRow0 = blockIdx.x * kRowsPerBlock;

    // Phase A: coalesced metadata stage — all 256 threads, one row each.
    {
        const int b = __ldg(&row_offsets[blockRow0 + t]);
        const int e = __ldg(&row_offsets[blockRow0 + t + 1]);
        s_beg[t] = b;
        s_end[t] = e;
        s_idx[t] = (b < e) ? __ldg(&vals[b]) : -1;
    }
    __syncthreads();

    const int warp = t >> 5;
    const int lane = t & 31;
    const char* tbl = reinterpret_cast<const char*>(table);
    char*       o   = reinterpret_cast<char*>(out);
    const unsigned laneOff = (unsigned)lane * 16u;

    // Phase B: warp owns 32 rows -> 8 batches of 4 independent 512B gathers.
#pragma unroll
    for (int batch = 0; batch < 8; ++batch) {
        const int base = warp * 32 + batch * kBatch;

        int idx[kBatch];
#pragma unroll
        for (int u = 0; u < kBatch; ++u) idx[u] = s_idx[base + u];  // LDS bcast

        // 4 independent 512B gathers — the only DRAM-latency ops in the loop.
        float4 v[kBatch];
#pragma unroll
        for (int u = 0; u < kBatch; ++u) {
            const unsigned i = (unsigned)((idx[u] >= 0) ? min(idx[u], kVocab - 1) : 0);
            v[u] = __ldg(reinterpret_cast<const float4*>(
                       tbl + i * (unsigned)kRowBytes + laneOff));
        }

#pragma unroll
        for (int u = 0; u < kBatch; ++u) {
            float4 acc = (idx[u] >= 0) ? v[u] : make_float4(0.f, 0.f, 0.f, 0.f);
            // Generic nnz>1 tail (absent in this dataset, kept for correctness).
            const int e = s_end[base + u];
            for (int j = s_beg[base + u] + 1; j < e; ++j) {
                int i = __ldg(&vals[j]);
                i = min(max(i, 0), kVocab - 1);
                const float4 tt = __ldg(reinterpret_cast<const float4*>(
                                      tbl + (unsigned)i * (unsigned)kRowBytes + laneOff));
                acc.x += tt.x; acc.y += tt.y; acc.z += tt.z; acc.w += tt.w;
            }
            const unsigned row = blockRow0 + (unsigned)(base + u);
            __stcs(reinterpret_cast<float4*>(
                       o + row * (unsigned)kRowBytes + laneOff), acc);
        }
    }
}

extern "C" void kernel_launch(void* const* d_in, const int* in_sizes, int n_in,
                              void* d_out, int out_size)
{
    const float* table = (const float*)d_in[0];
    const int*   offs  = (const int*)d_in[1];
    const int*   vals  = (const int*)d_in[2];
    float*       out   = (float*)d_out;

    (void)in_sizes; (void)n_in; (void)out_size;

    const int block = 256;
    const unsigned grid = (unsigned)(kNumRows / kRowsPerBlock);   // 832

    pe_gather_kernel<<<grid, block>>>(table, offs, vals, out);
}

// round 15
// speedup vs baseline: 1.0109x; 1.0109x over previous
#include <cuda_runtime.h>
#include <stdint.h>

// PluginEmbedding: sparse embedding lookup + per-row sum combine.
//   d_in[0] table         float32 [1000000, 128]
//   d_in[1] row_offsets   int32   [212993]
//   d_in[2] value_tensors int32   [212992]
// Output: float32 [212992, 128]
//
// R5-R14: every LDG-based design pins at DRAM ~60% / ~33us regardless of MLP
// -> per-SM L1tex outstanding-miss limit. This version moves the data path to
// TMA bulk copies: 128x 512B cp.async.bulk gathers per block (GMEM->SMEM, one
// mbarrier, no L1tex/register involvement), fixup for empty/nnz>1 rows, then
// ONE 64KB cp.async.bulk store (block's output rows are contiguous).

static constexpr int  kVocab        = 1000000;
static constexpr long long kNumRows = 8192LL * 26LL; // 212992
static constexpr int  kRowsPerBlock = 128;           // 1664 blocks (exact)
static constexpr int  kRowBytes     = 512;

static constexpr int  kBufBytes  = kRowsPerBlock * kRowBytes;     // 65536
static constexpr int  kMetaOff   = kBufBytes;                      // s_beg/s_end/s_idx
static constexpr int  kMbarOff   = kMetaOff + 3 * kRowsPerBlock * 4; // 67072
static constexpr int  kSmemTotal = kMbarOff + 16;                  // 67088

__device__ __forceinline__ unsigned smem_u32(const void* p) {
    unsigned a;
    asm("{ .reg .u64 t; cvta.to.shared.u64 t, %1; cvt.u32.u64 %0, t; }"
        : "=r"(a) : "l"(p));
    return a;
}

__global__ __launch_bounds__(256) void pe_gather_tma_kernel(
    const float* __restrict__ table,
    const int*   __restrict__ row_offsets,
    const int*   __restrict__ vals,
    float*       __restrict__ out)
{
    extern __shared__ char smem[];
    float4* buf   = reinterpret_cast<float4*>(smem);
    int*    s_beg = reinterpret_cast<int*>(smem + kMetaOff);
    int*    s_end = s_beg + kRowsPerBlock;
    int*    s_idx = s_end + kRowsPerBlock;
    const unsigned buf_u32  = smem_u32(smem);
    const unsigned mbar_u32 = smem_u32(smem + kMbarOff);

    const int t = threadIdx.x;
    const unsigned blockRow0 = blockIdx.x * kRowsPerBlock;

    // Metadata stage + mbarrier init. Keep per-thread meta in regs too.
    int myBeg = 0, myEnd = 0, myIdx = -1;
    if (t < kRowsPerBlock) {
        myBeg = __ldg(&row_offsets[blockRow0 + t]);
        myEnd = __ldg(&row_offsets[blockRow0 + t + 1]);
        myIdx = (myBeg < myEnd) ? __ldg(&vals[myBeg]) : -1;
        s_beg[t] = myBeg; s_end[t] = myEnd; s_idx[t] = myIdx;
    }
    if (t == 0) {
        asm volatile("mbarrier.init.shared.b64 [%0], %1;"
                     :: "r"(mbar_u32), "r"(1u) : "memory");
        asm volatile("mbarrier.arrive.expect_tx.shared.b64 _, [%0], %1;"
                     :: "r"(mbar_u32), "r"((unsigned)kBufBytes) : "memory");
    }
    __syncthreads();

    // TMA gather: thread r issues a 512B bulk copy for row r. Empty rows use
    // row 0 as a dummy source (fixed up below) so expect_tx stays constant.
    if (t < kRowsPerBlock) {
        const unsigned i = (unsigned)((myIdx >= 0) ? min(myIdx, kVocab - 1) : 0);
        const float* src = table + (long long)i * 128;
        asm volatile(
            "cp.async.bulk.shared::cta.global.mbarrier::complete_tx::bytes "
            "[%0], [%1], %2, [%3];"
            :: "r"(buf_u32 + (unsigned)t * (unsigned)kRowBytes),
               "l"(src), "r"((unsigned)kRowBytes), "r"(mbar_u32)
            : "memory");
    }

    // Wait for all 128 rows (64KB) to land.
    {
        unsigned done;
        asm volatile(
            "{\n\t.reg .pred p;\n\t"
            "mbarrier.try_wait.parity.acquire.cta.shared::cta.b64 p, [%1], %2;\n\t"
            "selp.b32 %0, 1, 0, p;\n\t}"
            : "=r"(done) : "r"(mbar_u32), "r"(0u) : "memory");
        if (!done) {
            asm volatile(
                "{\n\t.reg .pred P1;\n\t"
                "W_%=:\n\t"
                "mbarrier.try_wait.parity.acquire.cta.shared::cta.b64 P1, [%0], %1, 0x989680;\n\t"
                "@P1 bra.uni D_%=;\n\t"
                "bra.uni W_%=;\n\t"
                "D_%=:\n\t}"
                :: "r"(mbar_u32), "r"(0u) : "memory");
        }
    }

    // Fixup (generic correctness; cold in this dataset): warp w owns rows
    // [w*16, w*16+16). Zero empty rows, accumulate nnz>1 rows.
    {
        const int warp = t >> 5;
        const int lane = t & 31;
#pragma unroll
        for (int u = 0; u < 16; ++u) {
            const int r = warp * 16 + u;
            const int b = s_beg[r], e = s_end[r];
            if (e != b + 1) {
                float4 acc = (b < e) ? buf[r * 32 + lane]
                                     : make_float4(0.f, 0.f, 0.f, 0.f);
                for (int j = b + 1; j < e; ++j) {
                    int i = __ldg(&vals[j]);
                    i = min(max(i, 0), kVocab - 1);
                    const float4 v = __ldg(reinterpret_cast<const float4*>(
                                         table + (long long)i * 128) + lane);
                    acc.x += v.x; acc.y += v.y; acc.z += v.z; acc.w += v.w;
                }
                buf[r * 32 + lane] = acc;
            }
        }
    }
    __syncthreads();
    asm volatile("fence.proxy.async.shared::cta;" ::: "memory");

    // One contiguous 64KB TMA store: rows blockRow0..blockRow0+127.
    if (t == 0) {
        char* dst = reinterpret_cast<char*>(out) +
                    (unsigned long long)blockRow0 * kRowBytes;
        asm volatile(
            "cp.async.bulk.global.shared::cta.bulk_group [%0], [%1], %2;"
            :: "l"(dst), "r"(buf_u32), "r"((unsigned)kBufBytes) : "memory");
        asm volatile("cp.async.bulk.commit_group;" ::: "memory");
        asm volatile("cp.async.bulk.wait_group 0;" ::: "memory");
    }
}

extern "C" void kernel_launch(void* const* d_in, const int* in_sizes, int n_in,
                              void* d_out, int out_size)
{
    const float* table = (const float*)d_in[0];
    const int*   offs  = (const int*)d_in[1];
    const int*   vals  = (const int*)d_in[2];
    float*       out   = (float*)d_out;

    (void)in_sizes; (void)n_in; (void)out_size;

    cudaFuncSetAttribute(pe_gather_tma_kernel,
                         cudaFuncAttributeMaxDynamicSharedMemorySize, kSmemTotal);

    const int block = 256;
    const unsigned grid = (unsigned)(kNumRows / kRowsPerBlock);   // 1664

    pe_gather_tma_kernel<<<grid, block, kSmemTotal>>>(table, offs, vals, out);
}